// round 15
// baseline (speedup 1.0000x reference)
#include <cuda_runtime.h>
#include <cuda_bf16.h>
#include <math.h>

#define MAXN 100000
#define MAXE 1600000
#define IN_DIM 128
#define HID 64

#define PROP_BLOCKS 608          // 152 SMs * 4 CTAs (64-reg, 256 thr)
#define PROP_WARPS  (PROP_BLOCKS * 8)
#define GEMM_BLOCKS 608

#define COL2_SIZE (MAXE + 8 * MAXN + 32)

// sm_103a packed fp32 pair math (FFMA2 — not emitted by ptxas from C++).
// Used ONLY in prop (latency-bound); in the issue-bound GEMM, FFMA2's
// 3x64-bit operands (RF-banking rt=3 + pack MOVs) measurably regress.
#define FMA2(d, a, b, c) \
    asm("fma.rn.f32x2 %0, %1, %2, %3;" : "=l"(d) : "l"(a), "l"(b), "l"(c))
#define MUL2(d, a, b) \
    asm("mul.rn.f32x2 %0, %1, %2;" : "=l"(d) : "l"(a), "l"(b))
#define PK2(d, lo, hi) \
    asm("mov.b64 %0, {%1, %2};" : "=l"(d) : "r"(lo), "r"(hi))
#define UPK2(lo, hi, d) \
    asm("mov.b64 {%0, %1}, %2;" : "=r"(lo), "=r"(hi) : "l"(d))

typedef unsigned long long u64;

// Scratch (device globals — allocation-free rule).  Node index MAXN is the
// dummy pad node: xn[*][MAXN]=0, s[*][MAXN]=0, set once, never rewritten.
__device__ float g_h[(size_t)MAXN * HID];              // last-layer out (GEMM2)
__device__ float g_xn[2][(size_t)(MAXN + 1) * HID];    // ping-pong unit-norm
__device__ float g_s[2][MAXN + 1];                     // ping-pong norms (+eps)
__device__ int   g_rp[MAXN + 1];                       // CSR row pointer
__device__ int   g_col2[COL2_SIZE];                    // padded column indices

// ---------------------------------------------------------------------------
// Setup kernels
// ---------------------------------------------------------------------------
__global__ void rowptr_kernel(const int* __restrict__ row, int N, int E) {
    int t = blockIdx.x * blockDim.x + threadIdx.x;
    if (t > N) return;
    int lo = 0, hi = E;
    while (lo < hi) {
        int mid = (lo + hi) >> 1;
        if (row[mid] < t) lo = mid + 1; else hi = mid;
    }
    g_rp[t] = lo;
}

__global__ void padinit_kernel(int N) {   // zero the dummy node's slots
    int t = threadIdx.x;                  // 64 threads
    g_xn[0][(size_t)N * HID + t] = 0.f;
    g_xn[1][(size_t)N * HID + t] = 0.f;
    if (t == 0) { g_s[0][N] = 0.f; g_s[1][N] = 0.f; }
}

// fill ONLY the 8-entry gap after each node's segment (+16 tail) with dummy N
__global__ void gapfill_kernel(int N, int E) {
    int t = blockIdx.x * blockDim.x + threadIdx.x;
    if (t < 8 * N) {
        int node = t >> 3;
        g_col2[g_rp[node + 1] + 8 * node + (t & 7)] = N;
    } else if (t < 8 * N + 16) {
        g_col2[E + 8 * N + (t - 8 * N)] = N;   // tail safety for prefetch
    }
}

// scatter: segment i starts at rp[i] + 8*i  ->  dst(e) = e + 8*row(e)
__global__ void colscatter_kernel(const int* __restrict__ erow,
                                  const int* __restrict__ ecol, int E) {
    int e = blockIdx.x * blockDim.x + threadIdx.x;
    if (e < E) g_col2[e + 8 * erow[e]] = ecol[e];
}

// ---------------------------------------------------------------------------
// Skinny GEMM (known-good scalar-FFMA version): warp computes 8 rows/tile,
// single base pointer + immediate offsets, W-frag hoisted, rows in 2 batches
// of 4.  NORM: fused relu+normalize -> g_xn[0]/g_s[0].
// ---------------------------------------------------------------------------
template <int K, bool NORM>
__global__ void __launch_bounds__(256, 4)
gemm_kernel(const float* __restrict__ x_ext,
            const float* __restrict__ W,
            const float* __restrict__ b,
            float* __restrict__ out_ext, int N) {
    __shared__ float Wt[K * 64];
    for (int i = threadIdx.x; i < 64 * K; i += blockDim.x) {
        int o = i / K, k = i % K;
        Wt[k * 64 + o] = W[i];
    }
    __syncthreads();

    const float* xp = NORM ? x_ext : g_h;

    int warp = threadIdx.x >> 5, lane = threadIdx.x & 31;
    int gwarp = blockIdx.x * 8 + warp;
    int nwarps = gridDim.x * 8;
    int ntiles = (N + 7) / 8;
    float2 bias = ((const float2*)b)[lane];

    for (int tile = gwarp; tile < ntiles; tile += nwarps) {
        int row0 = tile * 8;

        float2 acc[8];
#pragma unroll
        for (int r = 0; r < 8; r++) acc[r] = make_float2(0.f, 0.f);

        if (row0 + 8 <= N) {
            const float* xr = xp + (size_t)row0 * K;   // one base pointer
#pragma unroll 2
            for (int k = 0; k < K; k += 4) {
                float2 w[4];
#pragma unroll
                for (int kk = 0; kk < 4; kk++)
                    w[kk] = *(const float2*)&Wt[(k + kk) * 64 + 2 * lane];

                {   // rows 0-3
                    float4 xv[4];
#pragma unroll
                    for (int r = 0; r < 4; r++)
                        xv[r] = *(const float4*)(xr + r * K + k);
#pragma unroll
                    for (int kk = 0; kk < 4; kk++)
#pragma unroll
                        for (int r = 0; r < 4; r++) {
                            float xs = ((const float*)&xv[r])[kk];
                            acc[r].x = fmaf(xs, w[kk].x, acc[r].x);
                            acc[r].y = fmaf(xs, w[kk].y, acc[r].y);
                        }
                }
                {   // rows 4-7
                    float4 xv[4];
#pragma unroll
                    for (int r = 0; r < 4; r++)
                        xv[r] = *(const float4*)(xr + (r + 4) * K + k);
#pragma unroll
                    for (int kk = 0; kk < 4; kk++)
#pragma unroll
                        for (int r = 0; r < 4; r++) {
                            float xs = ((const float*)&xv[r])[kk];
                            acc[r + 4].x = fmaf(xs, w[kk].x, acc[r + 4].x);
                            acc[r + 4].y = fmaf(xs, w[kk].y, acc[r + 4].y);
                        }
                }
            }
        } else {
            for (int k = 0; k < K; k++) {
                float2 w = *(const float2*)&Wt[k * 64 + 2 * lane];
#pragma unroll
                for (int r = 0; r < 8; r++) {
                    const float* p = xp + (size_t)min(row0 + r, N - 1) * K;
                    float xs = p[k];
                    acc[r].x = fmaf(xs, w.x, acc[r].x);
                    acc[r].y = fmaf(xs, w.y, acc[r].y);
                }
            }
        }

#pragma unroll
        for (int r = 0; r < 8; r++) {
            int row = row0 + r;
            if (row >= N) break;
            if (NORM) {
                float fx = fmaxf(acc[r].x + bias.x, 0.f);
                float fy = fmaxf(acc[r].y + bias.y, 0.f);
                float p = fx * fx + fy * fy;
                p += __shfl_xor_sync(0xffffffffu, p, 16);
                p += __shfl_xor_sync(0xffffffffu, p, 8);
                p += __shfl_xor_sync(0xffffffffu, p, 4);
                p += __shfl_xor_sync(0xffffffffu, p, 2);
                p += __shfl_xor_sync(0xffffffffu, p, 1);
                float nrm = sqrtf(p) + 1e-12f;
                float inv = 1.0f / nrm;
                ((float2*)g_xn[0])[(size_t)row * 32 + lane] =
                    make_float2(fx * inv, fy * inv);
                if (lane == 0) g_s[0][row] = nrm;
            } else {
                ((float2*)out_ext)[(size_t)row * 32 + lane] =
                    make_float2(acc[r].x + bias.x, acc[r].y + bias.y);
            }
        }
    }
}

// ---------------------------------------------------------------------------
// AGNN propagation + ReLU (+ fused normalize unless LAST).
// PERSISTENT WARPS; quarter-warp per edge; TWO chains (8 edges/iter);
// PADDED edge list (no per-edge predication; pad -> dummy node: exp(0)=1
// into ws, 0 into acc; exact pad count subtracted after merge).
// Mainloop math in PACKED f32x2 (FFMA2).
// ---------------------------------------------------------------------------
template <bool LAST>
__global__ void __launch_bounds__(256, 4)
prop_kernel(int src, int N) {
    int lane = threadIdx.x & 31;
    int q = lane >> 3, lq = lane & 7;
    int dst = src ^ 1;
    int gwarp = blockIdx.x * 8 + (threadIdx.x >> 5);

    const ulonglong2* __restrict__ xn2 = (const ulonglong2*)g_xn[src];
    const float*      __restrict__ sv  = g_s[src];

    for (int node = gwarp; node < N; node += PROP_WARPS) {
        int beg = g_rp[node], end = g_rp[node + 1];
        int deg = end - beg;

        if (deg == 0) {  // isolated node: out = 0 everywhere
            if (q == 0) {
                float4 z = make_float4(0.f, 0.f, 0.f, 0.f);
                if (LAST) {
                    ((float4*)g_h)[node * 16 + lq]     = z;
                    ((float4*)g_h)[node * 16 + 8 + lq] = z;
                } else {
                    ((float4*)g_xn[dst])[node * 16 + lq]     = z;
                    ((float4*)g_xn[dst])[node * 16 + 8 + lq] = z;
                    if (lq == 0) g_s[dst][node] = 1e-12f;
                }
            }
            continue;
        }

        const int* __restrict__ seg = g_col2 + (beg + 8 * node);
        int plen = (deg + 7) & ~7;

        // loop-invariant packed x fragments (dims 4lq.. and 32+4lq..)
        ulonglong2 Xa = xn2[node * 16 + lq];
        ulonglong2 Xb = xn2[node * 16 + 8 + lq];

        u64 A0 = 0ull, A1 = 0ull, B0 = 0ull, B1 = 0ull;  // packed acc pairs
        float ws = 0.f;

        // prologue: indices + s for the first iteration (always in-bounds)
        int   cA = __ldg(&seg[q]);
        int   cB = __ldg(&seg[4 + q]);
        float sA = __ldg(&sv[cA]);
        float sB = __ldg(&sv[cB]);

        for (int e0 = 0; e0 < plen; e0 += 8) {
            ulonglong2 YaA = xn2[cA * 16 + lq];
            ulonglong2 YbA = xn2[cA * 16 + 8 + lq];
            ulonglong2 YaB = xn2[cB * 16 + lq];
            ulonglong2 YbB = xn2[cB * 16 + 8 + lq];

            // prefetch next iteration (over-read is always in-bounds)
            int ncA = __ldg(&seg[e0 + 8 + q]);
            int ncB = __ldg(&seg[e0 + 12 + q]);
            float nsA = __ldg(&sv[ncA]);
            float nsB = __ldg(&sv[ncB]);

            // packed dot products (2 dims per FFMA2)
            u64 dA, dB;
            MUL2(dA, Xa.x, YaA.x);
            MUL2(dB, Xa.x, YaB.x);
            FMA2(dA, Xa.y, YaA.y, dA);  FMA2(dB, Xa.y, YaB.y, dB);
            FMA2(dA, Xb.x, YbA.x, dA);  FMA2(dB, Xb.x, YbB.x, dB);
            FMA2(dA, Xb.y, YbA.y, dA);  FMA2(dB, Xb.y, YbB.y, dB);

            unsigned loA, hiA, loB, hiB;
            UPK2(loA, hiA, dA);
            UPK2(loB, hiB, dB);
            float pA = __uint_as_float(loA) + __uint_as_float(hiA);
            float pB = __uint_as_float(loB) + __uint_as_float(hiB);

            pA += __shfl_xor_sync(0xffffffffu, pA, 1);
            pB += __shfl_xor_sync(0xffffffffu, pB, 1);
            pA += __shfl_xor_sync(0xffffffffu, pA, 2);
            pB += __shfl_xor_sync(0xffffffffu, pB, 2);
            pA += __shfl_xor_sync(0xffffffffu, pA, 4);
            pB += __shfl_xor_sync(0xffffffffu, pB, 4);

            float evA = __expf(pA);   // pad edge -> exp(0) = 1 exactly
            float evB = __expf(pB);
            ws += evA + evB;
            float wA = evA * sA, wB = evB * sB;  // pad: s=0 -> no acc effect

            u64 wA2, wB2;
            unsigned wAb = __float_as_uint(wA), wBb = __float_as_uint(wB);
            PK2(wA2, wAb, wAb);
            PK2(wB2, wBb, wBb);

            FMA2(A0, wA2, YaA.x, A0);  FMA2(A0, wB2, YaB.x, A0);
            FMA2(A1, wA2, YaA.y, A1);  FMA2(A1, wB2, YaB.y, A1);
            FMA2(B0, wA2, YbA.x, B0);  FMA2(B0, wB2, YbB.x, B0);
            FMA2(B1, wA2, YbA.y, B1);  FMA2(B1, wB2, YbB.y, B1);

            cA = ncA; cB = ncB; sA = nsA; sB = nsB;
        }

        // unpack accumulators, merge the 4 quarter-copies (butterfly 8, 16)
        float aa[8];
        {
            unsigned lo, hi;
            UPK2(lo, hi, A0); aa[0] = __uint_as_float(lo); aa[1] = __uint_as_float(hi);
            UPK2(lo, hi, A1); aa[2] = __uint_as_float(lo); aa[3] = __uint_as_float(hi);
            UPK2(lo, hi, B0); aa[4] = __uint_as_float(lo); aa[5] = __uint_as_float(hi);
            UPK2(lo, hi, B1); aa[6] = __uint_as_float(lo); aa[7] = __uint_as_float(hi);
        }
#pragma unroll
        for (int m = 8; m <= 16; m <<= 1) {
            ws += __shfl_xor_sync(0xffffffffu, ws, m);
#pragma unroll
            for (int d = 0; d < 8; d++)
                aa[d] += __shfl_xor_sync(0xffffffffu, aa[d], m);
        }

        ws -= (float)(plen - deg);               // remove pad contributions
        float inv = 1.0f / fmaxf(ws, 1e-12f);
        float o[8];
#pragma unroll
        for (int d = 0; d < 8; d++) o[d] = fmaxf(aa[d] * inv, 0.f);  // ReLU

        if (LAST) {
            if (q == 0) {
                ((float4*)g_h)[node * 16 + lq] =
                    make_float4(o[0], o[1], o[2], o[3]);
                ((float4*)g_h)[node * 16 + 8 + lq] =
                    make_float4(o[4], o[5], o[6], o[7]);
            }
        } else {
            // fused normalize for the next layer
            float pp = o[0] * o[0];
#pragma unroll
            for (int d = 1; d < 8; d++) pp = fmaf(o[d], o[d], pp);
            pp += __shfl_xor_sync(0xffffffffu, pp, 1);
            pp += __shfl_xor_sync(0xffffffffu, pp, 2);
            pp += __shfl_xor_sync(0xffffffffu, pp, 4);
            float nrm = sqrtf(pp) + 1e-12f;
            float iv = 1.0f / nrm;
            if (q == 0) {
                ((float4*)g_xn[dst])[node * 16 + lq] =
                    make_float4(o[0] * iv, o[1] * iv, o[2] * iv, o[3] * iv);
                ((float4*)g_xn[dst])[node * 16 + 8 + lq] =
                    make_float4(o[4] * iv, o[5] * iv, o[6] * iv, o[7] * iv);
                if (lq == 0) g_s[dst][node] = nrm;
            }
        }
    }
}

// ---------------------------------------------------------------------------
extern "C" void kernel_launch(void* const* d_in, const int* in_sizes, int n_in,
                              void* d_out, int out_size) {
    const float* x    = (const float*)d_in[0];
    const int*   erow = (const int*)d_in[1];
    const int*   ecol = (const int*)d_in[2];
    const float* W1   = (const float*)d_in[3];
    const float* b1   = (const float*)d_in[4];
    const float* W2   = (const float*)d_in[5];
    const float* b2   = (const float*)d_in[6];

    int N = in_sizes[0] / IN_DIM;
    int E = in_sizes[1];

    rowptr_kernel<<<(N + 1 + 255) / 256, 256>>>(erow, N, E);
    padinit_kernel<<<1, 64>>>(N);
    gapfill_kernel<<<(8 * N + 16 + 255) / 256, 256>>>(N, E);
    colscatter_kernel<<<(E + 255) / 256, 256>>>(erow, ecol, E);

    // h0 = relu(x @ W1^T + b1), fused normalize -> g_xn[0], g_s[0]
    gemm_kernel<IN_DIM, true><<<GEMM_BLOCKS, 256>>>(x, W1, b1, nullptr, N);

    prop_kernel<false><<<PROP_BLOCKS, 256>>>(0, N);
    prop_kernel<false><<<PROP_BLOCKS, 256>>>(1, N);
    prop_kernel<false><<<PROP_BLOCKS, 256>>>(0, N);
    prop_kernel<true ><<<PROP_BLOCKS, 256>>>(1, N);

    // out = g_h @ W2^T + b2
    gemm_kernel<HID, false><<<GEMM_BLOCKS, 256>>>(nullptr, W2, b2,
                                                  (float*)d_out, N);
}

// round 16
// speedup vs baseline: 1.6220x; 1.6220x over previous
#include <cuda_runtime.h>
#include <cuda_bf16.h>
#include <math.h>

#define MAXN 100000
#define MAXE 1600000
#define IN_DIM 128
#define HID 64

#define PROP_BLOCKS 608          // 152 SMs * 4 CTAs (64-reg, 256 thr)
#define PROP_WARPS  (PROP_BLOCKS * 8)
#define GEMM_BLOCKS 608

#define COL2_SIZE (MAXE + 8 * MAXN + 32)

// sm_103a packed fp32 pair math (FFMA2 — not emitted by ptxas from C++).
// Used ONLY in prop (latency-bound); in the issue-bound GEMM, FFMA2's
// 3x64-bit operands (RF-banking rt=3 + pack MOVs) measurably regress.
#define FMA2(d, a, b, c) \
    asm("fma.rn.f32x2 %0, %1, %2, %3;" : "=l"(d) : "l"(a), "l"(b), "l"(c))
#define MUL2(d, a, b) \
    asm("mul.rn.f32x2 %0, %1, %2;" : "=l"(d) : "l"(a), "l"(b))
#define PK2(d, lo, hi) \
    asm("mov.b64 %0, {%1, %2};" : "=l"(d) : "r"(lo), "r"(hi))
#define UPK2(lo, hi, d) \
    asm("mov.b64 {%0, %1}, %2;" : "=r"(lo), "=r"(hi) : "l"(d))

typedef unsigned long long u64;

// Scratch (device globals — allocation-free rule).  Node index MAXN is the
// dummy pad node: xn[*][MAXN]=0, s[*][MAXN]=0, set once, never rewritten.
__device__ float g_h[(size_t)MAXN * HID];              // last-layer out (GEMM2)
__device__ float g_xn[2][(size_t)(MAXN + 1) * HID];    // ping-pong unit-norm
__device__ float g_s[2][MAXN + 1];                     // ping-pong norms (+eps)
__device__ int   g_rp[MAXN + 1];                       // CSR row pointer
__device__ int   g_col2[COL2_SIZE];                    // padded column indices

// ---------------------------------------------------------------------------
// FUSED setup: one launch does scatter + rowptr + gapfill + tail + padinit.
//  - scatter (t < E):       dst = e + 8*erow[e]  (needs NO rp)
//  - rowptr  (t <= N):      own binary search -> g_rp[t]
//  - gapfill (1 <= t <= N): thread t just computed rp[t]; the 8-entry gap of
//      node t-1 starts at rp[t] + 8*(t-1).  Gap range [rp[i+1]+8i, +8) is
//      provably disjoint from every scatter target range [rp[j]+8j,
//      rp[j+1]+8j), so no ordering between phases is required.
//  - tail    (E <= t < E+16): pad past the last segment for prefetch reads
//  - padinit (t < 64):      zero the dummy node's xn/s slots
// ---------------------------------------------------------------------------
__global__ void setup_kernel(const int* __restrict__ erow,
                             const int* __restrict__ ecol, int N, int E) {
    int t = blockIdx.x * blockDim.x + threadIdx.x;

    if (t < E) g_col2[t + 8 * erow[t]] = ecol[t];

    if (t <= N) {
        int lo = 0, hi = E;
        while (lo < hi) {
            int mid = (lo + hi) >> 1;
            if (erow[mid] < t) lo = mid + 1; else hi = mid;
        }
        g_rp[t] = lo;
        if (t >= 1) {
            int base = lo + 8 * (t - 1);
#pragma unroll
            for (int j = 0; j < 8; j++) g_col2[base + j] = N;
        }
    }

    if (t >= E && t < E + 16) g_col2[8 * N + t] = N;   // = E+8N + (t-E)

    if (t < 64) {
        g_xn[0][(size_t)N * HID + t] = 0.f;
        g_xn[1][(size_t)N * HID + t] = 0.f;
        if (t == 0) { g_s[0][N] = 0.f; g_s[1][N] = 0.f; }
    }
}

// ---------------------------------------------------------------------------
// Skinny GEMM (known-good scalar-FFMA version): warp computes 8 rows/tile,
// single base pointer + immediate offsets, W-frag hoisted, rows in 2 batches
// of 4.  NORM: fused relu+normalize -> g_xn[0]/g_s[0].
// ---------------------------------------------------------------------------
template <int K, bool NORM>
__global__ void __launch_bounds__(256, 4)
gemm_kernel(const float* __restrict__ x_ext,
            const float* __restrict__ W,
            const float* __restrict__ b,
            float* __restrict__ out_ext, int N) {
    __shared__ float Wt[K * 64];
    for (int i = threadIdx.x; i < 64 * K; i += blockDim.x) {
        int o = i / K, k = i % K;
        Wt[k * 64 + o] = W[i];
    }
    __syncthreads();

    const float* xp = NORM ? x_ext : g_h;

    int warp = threadIdx.x >> 5, lane = threadIdx.x & 31;
    int gwarp = blockIdx.x * 8 + warp;
    int nwarps = gridDim.x * 8;
    int ntiles = (N + 7) / 8;
    float2 bias = ((const float2*)b)[lane];

    for (int tile = gwarp; tile < ntiles; tile += nwarps) {
        int row0 = tile * 8;

        float2 acc[8];
#pragma unroll
        for (int r = 0; r < 8; r++) acc[r] = make_float2(0.f, 0.f);

        if (row0 + 8 <= N) {
            const float* xr = xp + (size_t)row0 * K;   // one base pointer
#pragma unroll 2
            for (int k = 0; k < K; k += 4) {
                float2 w[4];
#pragma unroll
                for (int kk = 0; kk < 4; kk++)
                    w[kk] = *(const float2*)&Wt[(k + kk) * 64 + 2 * lane];

                {   // rows 0-3
                    float4 xv[4];
#pragma unroll
                    for (int r = 0; r < 4; r++)
                        xv[r] = *(const float4*)(xr + r * K + k);
#pragma unroll
                    for (int kk = 0; kk < 4; kk++)
#pragma unroll
                        for (int r = 0; r < 4; r++) {
                            float xs = ((const float*)&xv[r])[kk];
                            acc[r].x = fmaf(xs, w[kk].x, acc[r].x);
                            acc[r].y = fmaf(xs, w[kk].y, acc[r].y);
                        }
                }
                {   // rows 4-7
                    float4 xv[4];
#pragma unroll
                    for (int r = 0; r < 4; r++)
                        xv[r] = *(const float4*)(xr + (r + 4) * K + k);
#pragma unroll
                    for (int kk = 0; kk < 4; kk++)
#pragma unroll
                        for (int r = 0; r < 4; r++) {
                            float xs = ((const float*)&xv[r])[kk];
                            acc[r + 4].x = fmaf(xs, w[kk].x, acc[r + 4].x);
                            acc[r + 4].y = fmaf(xs, w[kk].y, acc[r + 4].y);
                        }
                }
            }
        } else {
            for (int k = 0; k < K; k++) {
                float2 w = *(const float2*)&Wt[k * 64 + 2 * lane];
#pragma unroll
                for (int r = 0; r < 8; r++) {
                    const float* p = xp + (size_t)min(row0 + r, N - 1) * K;
                    float xs = p[k];
                    acc[r].x = fmaf(xs, w.x, acc[r].x);
                    acc[r].y = fmaf(xs, w.y, acc[r].y);
                }
            }
        }

#pragma unroll
        for (int r = 0; r < 8; r++) {
            int row = row0 + r;
            if (row >= N) break;
            if (NORM) {
                float fx = fmaxf(acc[r].x + bias.x, 0.f);
                float fy = fmaxf(acc[r].y + bias.y, 0.f);
                float p = fx * fx + fy * fy;
                p += __shfl_xor_sync(0xffffffffu, p, 16);
                p += __shfl_xor_sync(0xffffffffu, p, 8);
                p += __shfl_xor_sync(0xffffffffu, p, 4);
                p += __shfl_xor_sync(0xffffffffu, p, 2);
                p += __shfl_xor_sync(0xffffffffu, p, 1);
                float nrm = sqrtf(p) + 1e-12f;
                float inv = 1.0f / nrm;
                ((float2*)g_xn[0])[(size_t)row * 32 + lane] =
                    make_float2(fx * inv, fy * inv);
                if (lane == 0) g_s[0][row] = nrm;
            } else {
                ((float2*)out_ext)[(size_t)row * 32 + lane] =
                    make_float2(acc[r].x + bias.x, acc[r].y + bias.y);
            }
        }
    }
}

// ---------------------------------------------------------------------------
// AGNN propagation + ReLU (+ fused normalize unless LAST).
// PERSISTENT WARPS; quarter-warp per edge; TWO chains (8 edges/iter);
// PADDED edge list (no per-edge predication; pad -> dummy node: exp(0)=1
// into ws, 0 into acc; exact pad count subtracted after merge).
// Mainloop math in PACKED f32x2 (FFMA2).
// ---------------------------------------------------------------------------
template <bool LAST>
__global__ void __launch_bounds__(256, 4)
prop_kernel(int src, int N) {
    int lane = threadIdx.x & 31;
    int q = lane >> 3, lq = lane & 7;
    int dst = src ^ 1;
    int gwarp = blockIdx.x * 8 + (threadIdx.x >> 5);

    const ulonglong2* __restrict__ xn2 = (const ulonglong2*)g_xn[src];
    const float*      __restrict__ sv  = g_s[src];

    for (int node = gwarp; node < N; node += PROP_WARPS) {
        int beg = g_rp[node], end = g_rp[node + 1];
        int deg = end - beg;

        if (deg == 0) {  // isolated node: out = 0 everywhere
            if (q == 0) {
                float4 z = make_float4(0.f, 0.f, 0.f, 0.f);
                if (LAST) {
                    ((float4*)g_h)[node * 16 + lq]     = z;
                    ((float4*)g_h)[node * 16 + 8 + lq] = z;
                } else {
                    ((float4*)g_xn[dst])[node * 16 + lq]     = z;
                    ((float4*)g_xn[dst])[node * 16 + 8 + lq] = z;
                    if (lq == 0) g_s[dst][node] = 1e-12f;
                }
            }
            continue;
        }

        const int* __restrict__ seg = g_col2 + (beg + 8 * node);
        int plen = (deg + 7) & ~7;

        // loop-invariant packed x fragments (dims 4lq.. and 32+4lq..)
        ulonglong2 Xa = xn2[node * 16 + lq];
        ulonglong2 Xb = xn2[node * 16 + 8 + lq];

        u64 A0 = 0ull, A1 = 0ull, B0 = 0ull, B1 = 0ull;  // packed acc pairs
        float ws = 0.f;

        // prologue: indices + s for the first iteration (always in-bounds)
        int   cA = __ldg(&seg[q]);
        int   cB = __ldg(&seg[4 + q]);
        float sA = __ldg(&sv[cA]);
        float sB = __ldg(&sv[cB]);

        for (int e0 = 0; e0 < plen; e0 += 8) {
            ulonglong2 YaA = xn2[cA * 16 + lq];
            ulonglong2 YbA = xn2[cA * 16 + 8 + lq];
            ulonglong2 YaB = xn2[cB * 16 + lq];
            ulonglong2 YbB = xn2[cB * 16 + 8 + lq];

            // prefetch next iteration (over-read is always in-bounds)
            int ncA = __ldg(&seg[e0 + 8 + q]);
            int ncB = __ldg(&seg[e0 + 12 + q]);
            float nsA = __ldg(&sv[ncA]);
            float nsB = __ldg(&sv[ncB]);

            // packed dot products (2 dims per FFMA2)
            u64 dA, dB;
            MUL2(dA, Xa.x, YaA.x);
            MUL2(dB, Xa.x, YaB.x);
            FMA2(dA, Xa.y, YaA.y, dA);  FMA2(dB, Xa.y, YaB.y, dB);
            FMA2(dA, Xb.x, YbA.x, dA);  FMA2(dB, Xb.x, YbB.x, dB);
            FMA2(dA, Xb.y, YbA.y, dA);  FMA2(dB, Xb.y, YbB.y, dB);

            unsigned loA, hiA, loB, hiB;
            UPK2(loA, hiA, dA);
            UPK2(loB, hiB, dB);
            float pA = __uint_as_float(loA) + __uint_as_float(hiA);
            float pB = __uint_as_float(loB) + __uint_as_float(hiB);

            pA += __shfl_xor_sync(0xffffffffu, pA, 1);
            pB += __shfl_xor_sync(0xffffffffu, pB, 1);
            pA += __shfl_xor_sync(0xffffffffu, pA, 2);
            pB += __shfl_xor_sync(0xffffffffu, pB, 2);
            pA += __shfl_xor_sync(0xffffffffu, pA, 4);
            pB += __shfl_xor_sync(0xffffffffu, pB, 4);

            float evA = __expf(pA);   // pad edge -> exp(0) = 1 exactly
            float evB = __expf(pB);
            ws += evA + evB;
            float wA = evA * sA, wB = evB * sB;  // pad: s=0 -> no acc effect

            u64 wA2, wB2;
            unsigned wAb = __float_as_uint(wA), wBb = __float_as_uint(wB);
            PK2(wA2, wAb, wAb);
            PK2(wB2, wBb, wBb);

            FMA2(A0, wA2, YaA.x, A0);  FMA2(A0, wB2, YaB.x, A0);
            FMA2(A1, wA2, YaA.y, A1);  FMA2(A1, wB2, YaB.y, A1);
            FMA2(B0, wA2, YbA.x, B0);  FMA2(B0, wB2, YbB.x, B0);
            FMA2(B1, wA2, YbA.y, B1);  FMA2(B1, wB2, YbB.y, B1);

            cA = ncA; cB = ncB; sA = nsA; sB = nsB;
        }

        // unpack accumulators, merge the 4 quarter-copies (butterfly 8, 16)
        float aa[8];
        {
            unsigned lo, hi;
            UPK2(lo, hi, A0); aa[0] = __uint_as_float(lo); aa[1] = __uint_as_float(hi);
            UPK2(lo, hi, A1); aa[2] = __uint_as_float(lo); aa[3] = __uint_as_float(hi);
            UPK2(lo, hi, B0); aa[4] = __uint_as_float(lo); aa[5] = __uint_as_float(hi);
            UPK2(lo, hi, B1); aa[6] = __uint_as_float(lo); aa[7] = __uint_as_float(hi);
        }
#pragma unroll
        for (int m = 8; m <= 16; m <<= 1) {
            ws += __shfl_xor_sync(0xffffffffu, ws, m);
#pragma unroll
            for (int d = 0; d < 8; d++)
                aa[d] += __shfl_xor_sync(0xffffffffu, aa[d], m);
        }

        ws -= (float)(plen - deg);               // remove pad contributions
        float inv = 1.0f / fmaxf(ws, 1e-12f);
        float o[8];
#pragma unroll
        for (int d = 0; d < 8; d++) o[d] = fmaxf(aa[d] * inv, 0.f);  // ReLU

        if (LAST) {
            if (q == 0) {
                ((float4*)g_h)[node * 16 + lq] =
                    make_float4(o[0], o[1], o[2], o[3]);
                ((float4*)g_h)[node * 16 + 8 + lq] =
                    make_float4(o[4], o[5], o[6], o[7]);
            }
        } else {
            // fused normalize for the next layer
            float pp = o[0] * o[0];
#pragma unroll
            for (int d = 1; d < 8; d++) pp = fmaf(o[d], o[d], pp);
            pp += __shfl_xor_sync(0xffffffffu, pp, 1);
            pp += __shfl_xor_sync(0xffffffffu, pp, 2);
            pp += __shfl_xor_sync(0xffffffffu, pp, 4);
            float nrm = sqrtf(pp) + 1e-12f;
            float iv = 1.0f / nrm;
            if (q == 0) {
                ((float4*)g_xn[dst])[node * 16 + lq] =
                    make_float4(o[0] * iv, o[1] * iv, o[2] * iv, o[3] * iv);
                ((float4*)g_xn[dst])[node * 16 + 8 + lq] =
                    make_float4(o[4] * iv, o[5] * iv, o[6] * iv, o[7] * iv);
                if (lq == 0) g_s[dst][node] = nrm;
            }
        }
    }
}

// ---------------------------------------------------------------------------
extern "C" void kernel_launch(void* const* d_in, const int* in_sizes, int n_in,
                              void* d_out, int out_size) {
    const float* x    = (const float*)d_in[0];
    const int*   erow = (const int*)d_in[1];
    const int*   ecol = (const int*)d_in[2];
    const float* W1   = (const float*)d_in[3];
    const float* b1   = (const float*)d_in[4];
    const float* W2   = (const float*)d_in[5];
    const float* b2   = (const float*)d_in[6];

    int N = in_sizes[0] / IN_DIM;
    int E = in_sizes[1];

    // one fused setup launch (scatter + rowptr + gapfill + tail + padinit)
    setup_kernel<<<(E + 16 + 255) / 256, 256>>>(erow, ecol, N, E);

    // h0 = relu(x @ W1^T + b1), fused normalize -> g_xn[0], g_s[0]
    gemm_kernel<IN_DIM, true><<<GEMM_BLOCKS, 256>>>(x, W1, b1, nullptr, N);

    prop_kernel<false><<<PROP_BLOCKS, 256>>>(0, N);
    prop_kernel<false><<<PROP_BLOCKS, 256>>>(1, N);
    prop_kernel<false><<<PROP_BLOCKS, 256>>>(0, N);
    prop_kernel<true ><<<PROP_BLOCKS, 256>>>(1, N);

    // out = g_h @ W2^T + b2
    gemm_kernel<HID, false><<<GEMM_BLOCKS, 256>>>(nullptr, W2, b2,
                                                  (float*)d_out, N);
}